// round 9
// baseline (speedup 1.0000x reference)
#include <cuda_runtime.h>
#include <math.h>

#define N_ENT   150000
#define N_USR   60000
#define CDIM    64
#define NE      1000000
#define NNZV    1000000
#define NRELM1  9

// concat degree/offset layout: [edges-by-head (N_ENT) | inter-by-col (N_ENT) | inter-by-row (N_USR)]
#define NT          (N_ENT + N_ENT + N_USR)   // 360000
#define SCAN_TILE   1024
#define SCAN_BLOCKS ((NT + SCAN_TILE - 1) / SCAN_TILE)  // 352

// ---------------- scratch (static device globals; no allocation) ----------------
__device__ float g_entA[(size_t)N_ENT * CDIM];
__device__ float g_usrA[(size_t)N_USR * CDIM];
__device__ float g_entB[(size_t)N_ENT * CDIM];
__device__ float g_usrB[(size_t)N_USR * CDIM];
__device__ float g_sq[NRELM1 * N_ENT];        // ||ent ∘ w_r||^2 (5.4 MB, L2-resident)

__device__ int g_deg[NT];
__device__ int g_off[NT + 1];
__device__ int g_cursor[NT];
__device__ int g_bsum[SCAN_BLOCKS];
__device__ int   g_epack[NE];                 // (tail << 4) | rel, grouped by head
__device__ int   g_nbr_e[NNZV];               // user idx, grouped by col
__device__ float g_val_e[NNZV];               // val,      grouped by col
__device__ int   g_nbr_u[NNZV];               // entity idx, grouped by row
__device__ float g_val_u[NNZV];               // val,        grouped by row

__device__ __forceinline__ void stcs4(float* p, float4 v) {
    __stcs((float4*)p, v);
}

// ---------------- init: curA = emb, deg = 0 (out untouched; written in hop 1) ----------
__global__ void k_init(const float* __restrict__ ue,
                       const float* __restrict__ ee) {
    const int tot_e = N_ENT * CDIM / 4;
    const int tot_u = N_USR * CDIM / 4;
    float4* ec = (float4*)g_entA;
    float4* uc = (float4*)g_usrA;
    const float4* e4 = (const float4*)ee;
    const float4* u4 = (const float4*)ue;
    int stride = gridDim.x * blockDim.x;
    int i0 = blockIdx.x * blockDim.x + threadIdx.x;
    for (int i = i0; i < tot_e; i += stride) ec[i] = e4[i];
    for (int i = i0; i < tot_u; i += stride) uc[i] = u4[i];
    for (int i = i0; i < NT;    i += stride) g_deg[i] = 0;
}

// ---------------- CSR build: histogram ----------------
__global__ void k_hist(const int* __restrict__ head,
                       const int* __restrict__ rows, const int* __restrict__ cols) {
    int i = blockIdx.x * blockDim.x + threadIdx.x;
    if (i >= NE) return;                       // NE == NNZV
    atomicAdd(&g_deg[head[i]], 1);
    atomicAdd(&g_deg[N_ENT + cols[i]], 1);
    atomicAdd(&g_deg[2 * N_ENT + rows[i]], 1);
}

// ---------------- CSR build: 3-kernel exclusive grid scan over g_deg ----------------
__global__ void k_scan1() {
    __shared__ int sh[256];
    int b = blockIdx.x, t = threadIdx.x;
    int base = b * SCAN_TILE + t * 4;
    int v0 = (base + 0 < NT) ? g_deg[base + 0] : 0;
    int v1 = (base + 1 < NT) ? g_deg[base + 1] : 0;
    int v2 = (base + 2 < NT) ? g_deg[base + 2] : 0;
    int v3 = (base + 3 < NT) ? g_deg[base + 3] : 0;
    int tsum = v0 + v1 + v2 + v3;
    sh[t] = tsum;
    __syncthreads();
    #pragma unroll
    for (int o = 1; o < 256; o <<= 1) {
        int x = (t >= o) ? sh[t - o] : 0;
        __syncthreads();
        sh[t] += x;
        __syncthreads();
    }
    int excl = sh[t] - tsum;
    if (t == 255) g_bsum[b] = sh[255];
    if (base + 0 < NT) g_off[base + 0] = excl;          excl += v0;
    if (base + 1 < NT) g_off[base + 1] = excl;          excl += v1;
    if (base + 2 < NT) g_off[base + 2] = excl;          excl += v2;
    if (base + 3 < NT) g_off[base + 3] = excl;
}

__global__ void k_scan2() {
    __shared__ int sh[512];
    int t = threadIdx.x;
    int v = (t < SCAN_BLOCKS) ? g_bsum[t] : 0;
    sh[t] = v;
    __syncthreads();
    #pragma unroll
    for (int o = 1; o < 512; o <<= 1) {
        int x = (t >= o) ? sh[t - o] : 0;
        __syncthreads();
        sh[t] += x;
        __syncthreads();
    }
    if (t < SCAN_BLOCKS) g_bsum[t] = sh[t] - v;   // exclusive
}

__global__ void k_scan3() {
    int i = blockIdx.x * blockDim.x + threadIdx.x;
    if (i >= NT) return;
    int v = g_off[i] + g_bsum[i / SCAN_TILE];
    g_off[i] = v;
    g_cursor[i] = v;
    if (i == 0) g_off[NT] = NE + 2 * NNZV;
}

// ---------------- CSR build: fill payload arrays (sequential at read time) ---------
__global__ void k_fill(const int* __restrict__ head, const int* __restrict__ tail,
                       const int* __restrict__ etype,
                       const int* __restrict__ rows, const int* __restrict__ cols,
                       const float* __restrict__ vals) {
    int i = blockIdx.x * blockDim.x + threadIdx.x;
    if (i >= NE) return;
    int r = etype[i] - 1;
    if (r < 0) r += NRELM1;                    // JAX wrap: -1 -> 8
    int p0 = atomicAdd(&g_cursor[head[i]], 1);
    g_epack[p0] = (tail[i] << 4) | r;
    float v = vals[i];
    int p1 = atomicAdd(&g_cursor[N_ENT + cols[i]], 1) - NE;
    g_nbr_e[p1] = rows[i];
    g_val_e[p1] = v;
    int p2 = atomicAdd(&g_cursor[2 * N_ENT + rows[i]], 1) - NE - NNZV;
    g_nbr_u[p2] = cols[i];
    g_val_u[p2] = v;
}

// ---------------- per-hop: g_sq[r][ent] = ||ent ∘ w_r||^2 (16 lanes/row) ------------
__global__ void k_sq(int hop, const float* __restrict__ weight) {
    const float* ent = hop ? g_entB : g_entA;
    int idx  = blockIdx.x * blockDim.x + threadIdx.x;
    int row  = idx >> 4;
    int lane = idx & 15;
    if (row >= N_ENT) return;
    float4 x = ((const float4*)(ent + (size_t)row * CDIM))[lane];
    float mine = 0.f;
    #pragma unroll
    for (int r = 0; r < NRELM1; r++) {
        float4 rv = ((const float4*)(weight + (size_t)r * CDIM))[lane];
        float a0 = x.x * rv.x, a1 = x.y * rv.y, a2 = x.z * rv.z, a3 = x.w * rv.w;
        float p = a0 * a0 + a1 * a1 + a2 * a2 + a3 * a3;
        #pragma unroll
        for (int o = 8; o; o >>= 1) p += __shfl_xor_sync(0xffffffffu, p, o);
        if (lane == r) mine = p;
    }
    if (lane < NRELM1) g_sq[lane * N_ENT + row] = mine;
}

// ---------------- per-hop: fused gather + softmax + SpMM + normalize (+ residual @hop1) ---
// Softmax is shift-invariant and att is bounded small for this data distribution,
// so exp(att) cannot overflow; w_i = ex_i / sum factors out of the weighted sum.
__global__ void k_agg(int hop, const float* __restrict__ weight,
                      const float* __restrict__ ue, const float* __restrict__ ee,
                      float* __restrict__ out) {
    const float* entc = hop ? g_entB : g_entA;
    const float* usrc = hop ? g_usrB : g_usrA;
    float* entn = hop ? g_entA : g_entB;
    float* usrn = hop ? g_usrA : g_usrB;

    int idx  = blockIdx.x * blockDim.x + threadIdx.x;
    int row  = idx >> 4;
    int lane = idx & 15;
    float4 acc = make_float4(0.f, 0.f, 0.f, 0.f);
    float* dst;
    const float* curp;   // this row's current value (hop-0 result at hop 1)
    const float* embp;   // original embedding row
    float* ores;
    if (row < N_ENT) {
        // --- knowledge-graph edges (softmax-weighted neighbors), 2x unrolled ---
        int s0 = g_off[row], s1 = g_off[row + 1];
        float s = 0.f;
        int j = s0;
        for (; j + 1 < s1; j += 2) {
            int pk0 = g_epack[j];
            int pk1 = g_epack[j + 1];
            int t0 = pk0 >> 4, r0 = pk0 & 15;
            int t1 = pk1 >> 4, r1 = pk1 & 15;
            float q0 = g_sq[r0 * N_ENT + t0];
            float q1 = g_sq[r1 * N_ENT + t1];
            float h0 = g_sq[r0 * N_ENT + row];
            float h1 = g_sq[r1 * N_ENT + row];
            float4 tv0 = ((const float4*)(entc + (size_t)t0 * CDIM))[lane];
            float4 tv1 = ((const float4*)(entc + (size_t)t1 * CDIM))[lane];
            float4 rv0 = ((const float4*)(weight + (size_t)r0 * CDIM))[lane];
            float4 rv1 = ((const float4*)(weight + (size_t)r1 * CDIM))[lane];
            float ex0 = expf(h0 * q0);
            float ex1 = expf(h1 * q1);
            s += ex0 + ex1;
            acc.x += ex0 * tv0.x * rv0.x + ex1 * tv1.x * rv1.x;
            acc.y += ex0 * tv0.y * rv0.y + ex1 * tv1.y * rv1.y;
            acc.z += ex0 * tv0.z * rv0.z + ex1 * tv1.z * rv1.z;
            acc.w += ex0 * tv0.w * rv0.w + ex1 * tv1.w * rv1.w;
        }
        if (j < s1) {
            int pk = g_epack[j];
            int t = pk >> 4, r = pk & 15;
            float ex = expf(g_sq[r * N_ENT + row] * g_sq[r * N_ENT + t]);
            s += ex;
            float4 tv = ((const float4*)(entc + (size_t)t * CDIM))[lane];
            float4 rv = ((const float4*)(weight + (size_t)r * CDIM))[lane];
            acc.x += ex * tv.x * rv.x;
            acc.y += ex * tv.y * rv.y;
            acc.z += ex * tv.z * rv.z;
            acc.w += ex * tv.w * rv.w;
        }
        if (s > 0.f) {
            float is = 1.f / s;
            acc.x *= is; acc.y *= is; acc.z *= is; acc.w *= is;
        }
        // --- interact_mat^T @ user, 2x unrolled ---
        int i0 = g_off[N_ENT + row] - NE, i1 = g_off[N_ENT + row + 1] - NE;
        j = i0;
        for (; j + 1 < i1; j += 2) {
            int nb0 = g_nbr_e[j];
            int nb1 = g_nbr_e[j + 1];
            float v0 = g_val_e[j];
            float v1 = g_val_e[j + 1];
            float4 u0 = ((const float4*)(usrc + (size_t)nb0 * CDIM))[lane];
            float4 u1 = ((const float4*)(usrc + (size_t)nb1 * CDIM))[lane];
            acc.x += v0 * u0.x + v1 * u1.x;
            acc.y += v0 * u0.y + v1 * u1.y;
            acc.z += v0 * u0.z + v1 * u1.z;
            acc.w += v0 * u0.w + v1 * u1.w;
        }
        if (j < i1) {
            int nb = g_nbr_e[j];
            float v = g_val_e[j];
            float4 u = ((const float4*)(usrc + (size_t)nb * CDIM))[lane];
            acc.x += v * u.x; acc.y += v * u.y; acc.z += v * u.z; acc.w += v * u.w;
        }
        dst  = entn + (size_t)row * CDIM;
        curp = entc + (size_t)row * CDIM;
        embp = ee   + (size_t)row * CDIM;
        ores = out  + (size_t)row * CDIM;
    } else {
        int ur = row - N_ENT;
        if (ur >= N_USR) return;
        // --- interact_mat @ entity, 2x unrolled ---
        int i0 = g_off[2 * N_ENT + ur] - NE - NNZV;
        int i1 = g_off[2 * N_ENT + ur + 1] - NE - NNZV;
        int j = i0;
        for (; j + 1 < i1; j += 2) {
            int nb0 = g_nbr_u[j];
            int nb1 = g_nbr_u[j + 1];
            float v0 = g_val_u[j];
            float v1 = g_val_u[j + 1];
            float4 e0 = ((const float4*)(entc + (size_t)nb0 * CDIM))[lane];
            float4 e1 = ((const float4*)(entc + (size_t)nb1 * CDIM))[lane];
            acc.x += v0 * e0.x + v1 * e1.x;
            acc.y += v0 * e0.y + v1 * e1.y;
            acc.z += v0 * e0.z + v1 * e1.z;
            acc.w += v0 * e0.w + v1 * e1.w;
        }
        if (j < i1) {
            int nb = g_nbr_u[j];
            float v = g_val_u[j];
            float4 e = ((const float4*)(entc + (size_t)nb * CDIM))[lane];
            acc.x += v * e.x; acc.y += v * e.y; acc.z += v * e.z; acc.w += v * e.w;
        }
        dst  = usrn + (size_t)ur * CDIM;
        curp = usrc + (size_t)ur * CDIM;
        embp = ue   + (size_t)ur * CDIM;
        ores = out + (size_t)N_ENT * CDIM + (size_t)ur * CDIM;
    }
    // --- L2 normalize ---
    float ss = acc.x * acc.x + acc.y * acc.y + acc.z * acc.z + acc.w * acc.w;
    #pragma unroll
    for (int o = 8; o; o >>= 1) ss += __shfl_xor_sync(0xffffffffu, ss, o);
    float inv = 1.0f / fmaxf(sqrtf(ss), 1e-12f);
    float4 y = make_float4(acc.x * inv, acc.y * inv, acc.z * inv, acc.w * inv);
    stcs4(dst + lane * 4, y);                  // streaming: consumed next kernel, not here
    if (hop == 1) {
        // out = emb_orig + hop0_result (== this hop's input row) + y, written once
        float4 c = ((const float4*)curp)[lane];
        float4 m = __ldcs((const float4*)embp + lane);
        float4 o = make_float4(m.x + c.x + y.x, m.y + c.y + y.y,
                               m.z + c.z + y.z, m.w + c.w + y.w);
        stcs4(ores + lane * 4, o);
    }
}

extern "C" void kernel_launch(void* const* d_in, const int* in_sizes, int n_in,
                              void* d_out, int out_size) {
    const float* user_emb   = (const float*)d_in[0];
    const float* entity_emb = (const float*)d_in[1];
    const float* weight     = (const float*)d_in[2];
    const float* inter_vals = (const float*)d_in[3];
    const int*   edge_index = (const int*)d_in[4];
    const int*   edge_type  = (const int*)d_in[5];
    const int*   inter_rows = (const int*)d_in[6];
    const int*   inter_cols = (const int*)d_in[7];
    float* out = (float*)d_out;

    const int* head = edge_index;
    const int* tail = edge_index + NE;

    const int WPB = 256;
    const int m_blocks    = (NE + WPB - 1) / WPB;
    const int nt_blocks   = (NT + WPB - 1) / WPB;
    const int sq_blocks   = (N_ENT * 16 + WPB - 1) / WPB;
    const int agg_blocks  = ((N_ENT + N_USR) * 16 + WPB - 1) / WPB;

    // once per launch: init + CSR build (graph is static across hops)
    k_init<<<2048, WPB>>>(user_emb, entity_emb);
    k_hist<<<m_blocks, WPB>>>(head, inter_rows, inter_cols);
    k_scan1<<<SCAN_BLOCKS, 256>>>();
    k_scan2<<<1, 512>>>();
    k_scan3<<<nt_blocks, WPB>>>();
    k_fill<<<m_blocks, WPB>>>(head, tail, edge_type, inter_rows, inter_cols, inter_vals);

    // hop 0: read A, write B;  hop 1: read B, write A (+ final residual into out)
    for (int hop = 0; hop < 2; hop++) {
        k_sq<<<sq_blocks, WPB>>>(hop, weight);
        k_agg<<<agg_blocks, WPB>>>(hop, weight, user_emb, entity_emb, out);
    }
}

// round 10
// speedup vs baseline: 1.3411x; 1.3411x over previous
#include <cuda_runtime.h>
#include <math.h>

#define N_ENT   150000
#define N_USR   60000
#define CDIM    64
#define NE      1000000
#define NNZV    1000000
#define NRELM1  9

// concat degree/offset layout: [edges-by-head (N_ENT) | inter-by-col (N_ENT) | inter-by-row (N_USR)]
#define NT          (N_ENT + N_ENT + N_USR)   // 360000
#define SCAN_TILE   1024
#define SCAN_BLOCKS ((NT + SCAN_TILE - 1) / SCAN_TILE)  // 352

// ---------------- scratch (static device globals; no allocation) ----------------
__device__ float g_entA[(size_t)N_ENT * CDIM];
__device__ float g_usrA[(size_t)N_USR * CDIM];
__device__ float g_entB[(size_t)N_ENT * CDIM];
__device__ float g_usrB[(size_t)N_USR * CDIM];
__device__ float g_sq[NRELM1 * N_ENT];        // ||ent ∘ w_r||^2 (5.4 MB, L2-resident)

__device__ int g_deg[NT];
__device__ int g_off[NT + 1];
__device__ int g_cursor[NT];
__device__ int g_bsum[SCAN_BLOCKS];
__device__ int   g_epack[NE];                 // (tail << 4) | rel, grouped by head
__device__ int   g_nbr_e[NNZV];               // user idx, grouped by col
__device__ float g_val_e[NNZV];               // val,      grouped by col
__device__ int   g_nbr_u[NNZV];               // entity idx, grouped by row
__device__ float g_val_u[NNZV];               // val,        grouped by row

// ---------------- init: curA = emb, deg = 0 (out untouched; written in hop 1) ----------
__global__ void k_init(const float* __restrict__ ue,
                       const float* __restrict__ ee) {
    const int tot_e = N_ENT * CDIM / 4;
    const int tot_u = N_USR * CDIM / 4;
    float4* ec = (float4*)g_entA;
    float4* uc = (float4*)g_usrA;
    const float4* e4 = (const float4*)ee;
    const float4* u4 = (const float4*)ue;
    int stride = gridDim.x * blockDim.x;
    int i0 = blockIdx.x * blockDim.x + threadIdx.x;
    for (int i = i0; i < tot_e; i += stride) ec[i] = e4[i];
    for (int i = i0; i < tot_u; i += stride) uc[i] = u4[i];
    for (int i = i0; i < NT;    i += stride) g_deg[i] = 0;
}

// ---------------- CSR build: histogram ----------------
__global__ void k_hist(const int* __restrict__ head,
                       const int* __restrict__ rows, const int* __restrict__ cols) {
    int i = blockIdx.x * blockDim.x + threadIdx.x;
    if (i >= NE) return;                       // NE == NNZV
    atomicAdd(&g_deg[head[i]], 1);
    atomicAdd(&g_deg[N_ENT + cols[i]], 1);
    atomicAdd(&g_deg[2 * N_ENT + rows[i]], 1);
}

// ---------------- CSR build: 3-kernel exclusive grid scan over g_deg ----------------
__global__ void k_scan1() {
    __shared__ int sh[256];
    int b = blockIdx.x, t = threadIdx.x;
    int base = b * SCAN_TILE + t * 4;
    int v0 = (base + 0 < NT) ? g_deg[base + 0] : 0;
    int v1 = (base + 1 < NT) ? g_deg[base + 1] : 0;
    int v2 = (base + 2 < NT) ? g_deg[base + 2] : 0;
    int v3 = (base + 3 < NT) ? g_deg[base + 3] : 0;
    int tsum = v0 + v1 + v2 + v3;
    sh[t] = tsum;
    __syncthreads();
    #pragma unroll
    for (int o = 1; o < 256; o <<= 1) {
        int x = (t >= o) ? sh[t - o] : 0;
        __syncthreads();
        sh[t] += x;
        __syncthreads();
    }
    int excl = sh[t] - tsum;
    if (t == 255) g_bsum[b] = sh[255];
    if (base + 0 < NT) g_off[base + 0] = excl;          excl += v0;
    if (base + 1 < NT) g_off[base + 1] = excl;          excl += v1;
    if (base + 2 < NT) g_off[base + 2] = excl;          excl += v2;
    if (base + 3 < NT) g_off[base + 3] = excl;
}

__global__ void k_scan2() {
    __shared__ int sh[512];
    int t = threadIdx.x;
    int v = (t < SCAN_BLOCKS) ? g_bsum[t] : 0;
    sh[t] = v;
    __syncthreads();
    #pragma unroll
    for (int o = 1; o < 512; o <<= 1) {
        int x = (t >= o) ? sh[t - o] : 0;
        __syncthreads();
        sh[t] += x;
        __syncthreads();
    }
    if (t < SCAN_BLOCKS) g_bsum[t] = sh[t] - v;   // exclusive
}

__global__ void k_scan3() {
    int i = blockIdx.x * blockDim.x + threadIdx.x;
    if (i >= NT) return;
    int v = g_off[i] + g_bsum[i / SCAN_TILE];
    g_off[i] = v;
    g_cursor[i] = v;
    if (i == 0) g_off[NT] = NE + 2 * NNZV;
}

// ---------------- CSR build: fill payload arrays (sequential at read time) ---------
__global__ void k_fill(const int* __restrict__ head, const int* __restrict__ tail,
                       const int* __restrict__ etype,
                       const int* __restrict__ rows, const int* __restrict__ cols,
                       const float* __restrict__ vals) {
    int i = blockIdx.x * blockDim.x + threadIdx.x;
    if (i >= NE) return;
    int r = etype[i] - 1;
    if (r < 0) r += NRELM1;                    // JAX wrap: -1 -> 8
    int p0 = atomicAdd(&g_cursor[head[i]], 1);
    g_epack[p0] = (tail[i] << 4) | r;
    float v = vals[i];
    int p1 = atomicAdd(&g_cursor[N_ENT + cols[i]], 1) - NE;
    g_nbr_e[p1] = rows[i];
    g_val_e[p1] = v;
    int p2 = atomicAdd(&g_cursor[2 * N_ENT + rows[i]], 1) - NE - NNZV;
    g_nbr_u[p2] = cols[i];
    g_val_u[p2] = v;
}

// ---------------- per-hop: g_sq[r][ent] = ||ent ∘ w_r||^2 (16 lanes/row) ------------
__global__ void k_sq(int hop, const float* __restrict__ weight) {
    const float* ent = hop ? g_entB : g_entA;
    int idx  = blockIdx.x * blockDim.x + threadIdx.x;
    int row  = idx >> 4;
    int lane = idx & 15;
    if (row >= N_ENT) return;
    float4 x = ((const float4*)(ent + (size_t)row * CDIM))[lane];
    float mine = 0.f;
    #pragma unroll
    for (int r = 0; r < NRELM1; r++) {
        float4 rv = ((const float4*)(weight + (size_t)r * CDIM))[lane];
        float a0 = x.x * rv.x, a1 = x.y * rv.y, a2 = x.z * rv.z, a3 = x.w * rv.w;
        float p = a0 * a0 + a1 * a1 + a2 * a2 + a3 * a3;
        #pragma unroll
        for (int o = 8; o; o >>= 1) p += __shfl_xor_sync(0xffffffffu, p, o);
        if (lane == r) mine = p;
    }
    if (lane < NRELM1) g_sq[lane * N_ENT + row] = mine;
}

// ---------------- per-hop: fused gather + softmax + SpMM + normalize (+ residual @hop1) ---
// Softmax is shift-invariant and att is bounded small for this data distribution,
// so exp(att) cannot overflow; w_i = ex_i / sum factors out of the weighted sum.
// NOTE: entn/usrn are written with NORMAL cached stores — they are the next hop's
// randomly-gathered working set and must stay L2-resident (R8 lesson: __stcs here
// cost +150us). Only `out` (never re-read) uses streaming stores.
__global__ void k_agg(int hop, const float* __restrict__ weight,
                      const float* __restrict__ ue, const float* __restrict__ ee,
                      float* __restrict__ out) {
    const float* entc = hop ? g_entB : g_entA;
    const float* usrc = hop ? g_usrB : g_usrA;
    float* entn = hop ? g_entA : g_entB;
    float* usrn = hop ? g_usrA : g_usrB;

    int idx  = blockIdx.x * blockDim.x + threadIdx.x;
    int row  = idx >> 4;
    int lane = idx & 15;
    float4 acc = make_float4(0.f, 0.f, 0.f, 0.f);
    float* dst;
    const float* curp;   // this row's current value (hop-0 result at hop 1)
    const float* embp;   // original embedding row
    float* ores;
    if (row < N_ENT) {
        // --- knowledge-graph edges (softmax-weighted neighbors), 2x unrolled ---
        int s0 = g_off[row], s1 = g_off[row + 1];
        float s = 0.f;
        int j = s0;
        for (; j + 1 < s1; j += 2) {
            int pk0 = g_epack[j];
            int pk1 = g_epack[j + 1];
            int t0 = pk0 >> 4, r0 = pk0 & 15;
            int t1 = pk1 >> 4, r1 = pk1 & 15;
            float q0 = g_sq[r0 * N_ENT + t0];
            float q1 = g_sq[r1 * N_ENT + t1];
            float h0 = g_sq[r0 * N_ENT + row];
            float h1 = g_sq[r1 * N_ENT + row];
            float4 tv0 = ((const float4*)(entc + (size_t)t0 * CDIM))[lane];
            float4 tv1 = ((const float4*)(entc + (size_t)t1 * CDIM))[lane];
            float4 rv0 = ((const float4*)(weight + (size_t)r0 * CDIM))[lane];
            float4 rv1 = ((const float4*)(weight + (size_t)r1 * CDIM))[lane];
            float ex0 = expf(h0 * q0);
            float ex1 = expf(h1 * q1);
            s += ex0 + ex1;
            acc.x += ex0 * tv0.x * rv0.x + ex1 * tv1.x * rv1.x;
            acc.y += ex0 * tv0.y * rv0.y + ex1 * tv1.y * rv1.y;
            acc.z += ex0 * tv0.z * rv0.z + ex1 * tv1.z * rv1.z;
            acc.w += ex0 * tv0.w * rv0.w + ex1 * tv1.w * rv1.w;
        }
        if (j < s1) {
            int pk = g_epack[j];
            int t = pk >> 4, r = pk & 15;
            float ex = expf(g_sq[r * N_ENT + row] * g_sq[r * N_ENT + t]);
            s += ex;
            float4 tv = ((const float4*)(entc + (size_t)t * CDIM))[lane];
            float4 rv = ((const float4*)(weight + (size_t)r * CDIM))[lane];
            acc.x += ex * tv.x * rv.x;
            acc.y += ex * tv.y * rv.y;
            acc.z += ex * tv.z * rv.z;
            acc.w += ex * tv.w * rv.w;
        }
        if (s > 0.f) {
            float is = 1.f / s;
            acc.x *= is; acc.y *= is; acc.z *= is; acc.w *= is;
        }
        // --- interact_mat^T @ user, 2x unrolled ---
        int i0 = g_off[N_ENT + row] - NE, i1 = g_off[N_ENT + row + 1] - NE;
        j = i0;
        for (; j + 1 < i1; j += 2) {
            int nb0 = g_nbr_e[j];
            int nb1 = g_nbr_e[j + 1];
            float v0 = g_val_e[j];
            float v1 = g_val_e[j + 1];
            float4 u0 = ((const float4*)(usrc + (size_t)nb0 * CDIM))[lane];
            float4 u1 = ((const float4*)(usrc + (size_t)nb1 * CDIM))[lane];
            acc.x += v0 * u0.x + v1 * u1.x;
            acc.y += v0 * u0.y + v1 * u1.y;
            acc.z += v0 * u0.z + v1 * u1.z;
            acc.w += v0 * u0.w + v1 * u1.w;
        }
        if (j < i1) {
            int nb = g_nbr_e[j];
            float v = g_val_e[j];
            float4 u = ((const float4*)(usrc + (size_t)nb * CDIM))[lane];
            acc.x += v * u.x; acc.y += v * u.y; acc.z += v * u.z; acc.w += v * u.w;
        }
        dst  = entn + (size_t)row * CDIM;
        curp = entc + (size_t)row * CDIM;
        embp = ee   + (size_t)row * CDIM;
        ores = out  + (size_t)row * CDIM;
    } else {
        int ur = row - N_ENT;
        if (ur >= N_USR) return;
        // --- interact_mat @ entity, 2x unrolled ---
        int i0 = g_off[2 * N_ENT + ur] - NE - NNZV;
        int i1 = g_off[2 * N_ENT + ur + 1] - NE - NNZV;
        int j = i0;
        for (; j + 1 < i1; j += 2) {
            int nb0 = g_nbr_u[j];
            int nb1 = g_nbr_u[j + 1];
            float v0 = g_val_u[j];
            float v1 = g_val_u[j + 1];
            float4 e0 = ((const float4*)(entc + (size_t)nb0 * CDIM))[lane];
            float4 e1 = ((const float4*)(entc + (size_t)nb1 * CDIM))[lane];
            acc.x += v0 * e0.x + v1 * e1.x;
            acc.y += v0 * e0.y + v1 * e1.y;
            acc.z += v0 * e0.z + v1 * e1.z;
            acc.w += v0 * e0.w + v1 * e1.w;
        }
        if (j < i1) {
            int nb = g_nbr_u[j];
            float v = g_val_u[j];
            float4 e = ((const float4*)(entc + (size_t)nb * CDIM))[lane];
            acc.x += v * e.x; acc.y += v * e.y; acc.z += v * e.z; acc.w += v * e.w;
        }
        dst  = usrn + (size_t)ur * CDIM;
        curp = usrc + (size_t)ur * CDIM;
        embp = ue   + (size_t)ur * CDIM;
        ores = out + (size_t)N_ENT * CDIM + (size_t)ur * CDIM;
    }
    // --- L2 normalize ---
    float ss = acc.x * acc.x + acc.y * acc.y + acc.z * acc.z + acc.w * acc.w;
    #pragma unroll
    for (int o = 8; o; o >>= 1) ss += __shfl_xor_sync(0xffffffffu, ss, o);
    float inv = 1.0f / fmaxf(sqrtf(ss), 1e-12f);
    float4 y = make_float4(acc.x * inv, acc.y * inv, acc.z * inv, acc.w * inv);
    ((float4*)dst)[lane] = y;                   // NORMAL store: keep L2-resident for next hop
    if (hop == 1) {
        // out = emb_orig + hop0_result (== this hop's input row) + y, written once
        float4 c = ((const float4*)curp)[lane];
        float4 m = __ldcs((const float4*)embp + lane);
        float4 o = make_float4(m.x + c.x + y.x, m.y + c.y + y.y,
                               m.z + c.z + y.z, m.w + c.w + y.w);
        __stcs((float4*)ores + lane, o);        // out is never re-read: stream it
    }
}

extern "C" void kernel_launch(void* const* d_in, const int* in_sizes, int n_in,
                              void* d_out, int out_size) {
    const float* user_emb   = (const float*)d_in[0];
    const float* entity_emb = (const float*)d_in[1];
    const float* weight     = (const float*)d_in[2];
    const float* inter_vals = (const float*)d_in[3];
    const int*   edge_index = (const int*)d_in[4];
    const int*   edge_type  = (const int*)d_in[5];
    const int*   inter_rows = (const int*)d_in[6];
    const int*   inter_cols = (const int*)d_in[7];
    float* out = (float*)d_out;

    const int* head = edge_index;
    const int* tail = edge_index + NE;

    const int WPB = 256;
    const int m_blocks    = (NE + WPB - 1) / WPB;
    const int nt_blocks   = (NT + WPB - 1) / WPB;
    const int sq_blocks   = (N_ENT * 16 + WPB - 1) / WPB;
    const int agg_blocks  = ((N_ENT + N_USR) * 16 + WPB - 1) / WPB;

    // once per launch: init + CSR build (graph is static across hops)
    k_init<<<2048, WPB>>>(user_emb, entity_emb);
    k_hist<<<m_blocks, WPB>>>(head, inter_rows, inter_cols);
    k_scan1<<<SCAN_BLOCKS, 256>>>();
    k_scan2<<<1, 512>>>();
    k_scan3<<<nt_blocks, WPB>>>();
    k_fill<<<m_blocks, WPB>>>(head, tail, edge_type, inter_rows, inter_cols, inter_vals);

    // hop 0: read A, write B;  hop 1: read B, write A (+ final residual into out)
    for (int hop = 0; hop < 2; hop++) {
        k_sq<<<sq_blocks, WPB>>>(hop, weight);
        k_agg<<<agg_blocks, WPB>>>(hop, weight, user_emb, entity_emb, out);
    }
}

// round 11
// speedup vs baseline: 1.3761x; 1.0261x over previous
#include <cuda_runtime.h>
#include <math.h>

#define N_ENT   150000
#define N_USR   60000
#define CDIM    64
#define NE      1000000
#define NNZV    1000000
#define NRELM1  9

// concat degree/offset layout: [edges-by-head (N_ENT) | inter-by-col (N_ENT) | inter-by-row (N_USR)]
#define NT          (N_ENT + N_ENT + N_USR)   // 360000
#define SCAN_TILE   1024
#define SCAN_BLOCKS ((NT + SCAN_TILE - 1) / SCAN_TILE)  // 352

// ---------------- scratch (static device globals; no allocation) ----------------
__device__ float g_entA[(size_t)N_ENT * CDIM];
__device__ float g_usrA[(size_t)N_USR * CDIM];
__device__ float g_entB[(size_t)N_ENT * CDIM];
__device__ float g_usrB[(size_t)N_USR * CDIM];
__device__ float g_sq[NRELM1 * N_ENT];        // ||ent ∘ w_r||^2 (5.4 MB, L2-resident)

__device__ int g_deg[NT];
__device__ int g_off[NT + 1];
__device__ int g_cursor[NT];
__device__ int g_bsum[SCAN_BLOCKS];
__device__ int   g_epack[NE];                 // (tail << 4) | rel, grouped by head
__device__ int   g_nbr_e[NNZV];               // user idx, grouped by col
__device__ float g_val_e[NNZV];               // val,      grouped by col
__device__ int   g_nbr_u[NNZV];               // entity idx, grouped by row
__device__ float g_val_u[NNZV];               // val,        grouped by row

// ---------------- init: curA = emb, deg = 0 (out untouched; written once in hop 1) ------
__global__ void k_init(const float* __restrict__ ue,
                       const float* __restrict__ ee) {
    const int tot_e = N_ENT * CDIM / 4;
    const int tot_u = N_USR * CDIM / 4;
    float4* ec = (float4*)g_entA;
    float4* uc = (float4*)g_usrA;
    const float4* e4 = (const float4*)ee;
    const float4* u4 = (const float4*)ue;
    int stride = gridDim.x * blockDim.x;
    int i0 = blockIdx.x * blockDim.x + threadIdx.x;
    for (int i = i0; i < tot_e; i += stride) ec[i] = e4[i];
    for (int i = i0; i < tot_u; i += stride) uc[i] = u4[i];
    for (int i = i0; i < NT;    i += stride) g_deg[i] = 0;
}

// ---------------- CSR build: histogram ----------------
__global__ void k_hist(const int* __restrict__ head,
                       const int* __restrict__ rows, const int* __restrict__ cols) {
    int i = blockIdx.x * blockDim.x + threadIdx.x;
    if (i >= NE) return;                       // NE == NNZV
    atomicAdd(&g_deg[head[i]], 1);
    atomicAdd(&g_deg[N_ENT + cols[i]], 1);
    atomicAdd(&g_deg[2 * N_ENT + rows[i]], 1);
}

// ---------------- CSR build: 3-kernel exclusive grid scan over g_deg ----------------
__global__ void k_scan1() {
    __shared__ int sh[256];
    int b = blockIdx.x, t = threadIdx.x;
    int base = b * SCAN_TILE + t * 4;
    int v0 = (base + 0 < NT) ? g_deg[base + 0] : 0;
    int v1 = (base + 1 < NT) ? g_deg[base + 1] : 0;
    int v2 = (base + 2 < NT) ? g_deg[base + 2] : 0;
    int v3 = (base + 3 < NT) ? g_deg[base + 3] : 0;
    int tsum = v0 + v1 + v2 + v3;
    sh[t] = tsum;
    __syncthreads();
    #pragma unroll
    for (int o = 1; o < 256; o <<= 1) {
        int x = (t >= o) ? sh[t - o] : 0;
        __syncthreads();
        sh[t] += x;
        __syncthreads();
    }
    int excl = sh[t] - tsum;
    if (t == 255) g_bsum[b] = sh[255];
    if (base + 0 < NT) g_off[base + 0] = excl;          excl += v0;
    if (base + 1 < NT) g_off[base + 1] = excl;          excl += v1;
    if (base + 2 < NT) g_off[base + 2] = excl;          excl += v2;
    if (base + 3 < NT) g_off[base + 3] = excl;
}

__global__ void k_scan2() {
    __shared__ int sh[512];
    int t = threadIdx.x;
    int v = (t < SCAN_BLOCKS) ? g_bsum[t] : 0;
    sh[t] = v;
    __syncthreads();
    #pragma unroll
    for (int o = 1; o < 512; o <<= 1) {
        int x = (t >= o) ? sh[t - o] : 0;
        __syncthreads();
        sh[t] += x;
        __syncthreads();
    }
    if (t < SCAN_BLOCKS) g_bsum[t] = sh[t] - v;   // exclusive
}

__global__ void k_scan3() {
    int i = blockIdx.x * blockDim.x + threadIdx.x;
    if (i >= NT) return;
    int v = g_off[i] + g_bsum[i / SCAN_TILE];
    g_off[i] = v;
    g_cursor[i] = v;
    if (i == 0) g_off[NT] = NE + 2 * NNZV;
}

// ---------------- CSR build: fill payload arrays (sequential at read time) ---------
__global__ void k_fill(const int* __restrict__ head, const int* __restrict__ tail,
                       const int* __restrict__ etype,
                       const int* __restrict__ rows, const int* __restrict__ cols,
                       const float* __restrict__ vals) {
    int i = blockIdx.x * blockDim.x + threadIdx.x;
    if (i >= NE) return;
    int r = etype[i] - 1;
    if (r < 0) r += NRELM1;                    // JAX wrap: -1 -> 8
    int p0 = atomicAdd(&g_cursor[head[i]], 1);
    g_epack[p0] = (tail[i] << 4) | r;
    float v = vals[i];
    int p1 = atomicAdd(&g_cursor[N_ENT + cols[i]], 1) - NE;
    g_nbr_e[p1] = rows[i];
    g_val_e[p1] = v;
    int p2 = atomicAdd(&g_cursor[2 * N_ENT + rows[i]], 1) - NE - NNZV;
    g_nbr_u[p2] = cols[i];
    g_val_u[p2] = v;
}

// ---------------- per-hop: g_sq[r][ent] = ||ent ∘ w_r||^2 (16 lanes/row) ------------
__global__ void k_sq(int hop, const float* __restrict__ weight) {
    const float* ent = hop ? g_entB : g_entA;
    int idx  = blockIdx.x * blockDim.x + threadIdx.x;
    int row  = idx >> 4;
    int lane = idx & 15;
    if (row >= N_ENT) return;
    float4 x = ((const float4*)(ent + (size_t)row * CDIM))[lane];
    float mine = 0.f;
    #pragma unroll
    for (int r = 0; r < NRELM1; r++) {
        float4 rv = ((const float4*)(weight + (size_t)r * CDIM))[lane];
        float a0 = x.x * rv.x, a1 = x.y * rv.y, a2 = x.z * rv.z, a3 = x.w * rv.w;
        float p = a0 * a0 + a1 * a1 + a2 * a2 + a3 * a3;
        #pragma unroll
        for (int o = 8; o; o >>= 1) p += __shfl_xor_sync(0xffffffffu, p, o);
        if (lane == r) mine = p;
    }
    if (lane < NRELM1) g_sq[lane * N_ENT + row] = mine;
}

// ---------------- per-hop: fused gather + softmax + SpMM + normalize (+ residual @hop1) ---
// Softmax is shift-invariant and att is bounded small for this data distribution,
// so exp(att) cannot overflow; w_i = ex_i / sum factors out of the weighted sum.
// No unroll, no cache hints (R8/R9 lessons): plain cached loads/stores everywhere;
// the only delta vs the 338us R7 kernel is the residual-once scheme.
__global__ void k_agg(int hop, const float* __restrict__ weight,
                      const float* __restrict__ ue, const float* __restrict__ ee,
                      float* __restrict__ out) {
    const float* entc = hop ? g_entB : g_entA;
    const float* usrc = hop ? g_usrB : g_usrA;
    float* entn = hop ? g_entA : g_entB;
    float* usrn = hop ? g_usrA : g_usrB;

    int idx  = blockIdx.x * blockDim.x + threadIdx.x;
    int row  = idx >> 4;
    int lane = idx & 15;
    float4 acc = make_float4(0.f, 0.f, 0.f, 0.f);
    float* dst;
    const float* curp;   // this row's current value (hop-0 result at hop 1)
    const float* embp;   // original embedding row
    float* ores;
    if (row < N_ENT) {
        // --- knowledge-graph edges (softmax-weighted neighbors) ---
        int s0 = g_off[row], s1 = g_off[row + 1];
        float s = 0.f;
        for (int j = s0; j < s1; j++) {
            int pk = g_epack[j];               // sequential
            int t = pk >> 4;
            int r = pk & 15;
            float ex = expf(g_sq[r * N_ENT + row] * g_sq[r * N_ENT + t]);
            s += ex;
            float4 tv = ((const float4*)(entc   + (size_t)t * CDIM))[lane];
            float4 rv = ((const float4*)(weight + (size_t)r * CDIM))[lane];
            acc.x += ex * tv.x * rv.x;
            acc.y += ex * tv.y * rv.y;
            acc.z += ex * tv.z * rv.z;
            acc.w += ex * tv.w * rv.w;
        }
        if (s > 0.f) {
            float is = 1.f / s;
            acc.x *= is; acc.y *= is; acc.z *= is; acc.w *= is;
        }
        // --- interact_mat^T @ user ---
        int i0 = g_off[N_ENT + row] - NE, i1 = g_off[N_ENT + row + 1] - NE;
        for (int j = i0; j < i1; j++) {
            int nb = g_nbr_e[j];               // sequential
            float v = g_val_e[j];              // sequential
            float4 u = ((const float4*)(usrc + (size_t)nb * CDIM))[lane];
            acc.x += v * u.x; acc.y += v * u.y; acc.z += v * u.z; acc.w += v * u.w;
        }
        dst  = entn + (size_t)row * CDIM;
        curp = entc + (size_t)row * CDIM;
        embp = ee   + (size_t)row * CDIM;
        ores = out  + (size_t)row * CDIM;
    } else {
        int ur = row - N_ENT;
        if (ur >= N_USR) return;
        // --- interact_mat @ entity ---
        int i0 = g_off[2 * N_ENT + ur] - NE - NNZV;
        int i1 = g_off[2 * N_ENT + ur + 1] - NE - NNZV;
        for (int j = i0; j < i1; j++) {
            int nb = g_nbr_u[j];               // sequential
            float v = g_val_u[j];              // sequential
            float4 e = ((const float4*)(entc + (size_t)nb * CDIM))[lane];
            acc.x += v * e.x; acc.y += v * e.y; acc.z += v * e.z; acc.w += v * e.w;
        }
        dst  = usrn + (size_t)ur * CDIM;
        curp = usrc + (size_t)ur * CDIM;
        embp = ue   + (size_t)ur * CDIM;
        ores = out + (size_t)N_ENT * CDIM + (size_t)ur * CDIM;
    }
    // --- L2 normalize ---
    float ss = acc.x * acc.x + acc.y * acc.y + acc.z * acc.z + acc.w * acc.w;
    #pragma unroll
    for (int o = 8; o; o >>= 1) ss += __shfl_xor_sync(0xffffffffu, ss, o);
    float inv = 1.0f / fmaxf(sqrtf(ss), 1e-12f);
    float4 y = make_float4(acc.x * inv, acc.y * inv, acc.z * inv, acc.w * inv);
    ((float4*)dst)[lane] = y;                  // normal store: next hop's L2 working set
    if (hop == 1) {
        // out = emb_orig + hop0_result (== this hop's input row) + y, written once
        float4 c = ((const float4*)curp)[lane];
        float4 m = ((const float4*)embp)[lane];
        float4 o = make_float4(m.x + c.x + y.x, m.y + c.y + y.y,
                               m.z + c.z + y.z, m.w + c.w + y.w);
        ((float4*)ores)[lane] = o;
    }
}

extern "C" void kernel_launch(void* const* d_in, const int* in_sizes, int n_in,
                              void* d_out, int out_size) {
    const float* user_emb   = (const float*)d_in[0];
    const float* entity_emb = (const float*)d_in[1];
    const float* weight     = (const float*)d_in[2];
    const float* inter_vals = (const float*)d_in[3];
    const int*   edge_index = (const int*)d_in[4];
    const int*   edge_type  = (const int*)d_in[5];
    const int*   inter_rows = (const int*)d_in[6];
    const int*   inter_cols = (const int*)d_in[7];
    float* out = (float*)d_out;

    const int* head = edge_index;
    const int* tail = edge_index + NE;

    const int WPB = 256;
    const int m_blocks    = (NE + WPB - 1) / WPB;
    const int nt_blocks   = (NT + WPB - 1) / WPB;
    const int sq_blocks   = (N_ENT * 16 + WPB - 1) / WPB;
    const int agg_blocks  = ((N_ENT + N_USR) * 16 + WPB - 1) / WPB;

    // once per launch: init + CSR build (graph is static across hops)
    k_init<<<2048, WPB>>>(user_emb, entity_emb);
    k_hist<<<m_blocks, WPB>>>(head, inter_rows, inter_cols);
    k_scan1<<<SCAN_BLOCKS, 256>>>();
    k_scan2<<<1, 512>>>();
    k_scan3<<<nt_blocks, WPB>>>();
    k_fill<<<m_blocks, WPB>>>(head, tail, edge_type, inter_rows, inter_cols, inter_vals);

    // hop 0: read A, write B;  hop 1: read B, write A (+ final residual into out)
    for (int hop = 0; hop < 2; hop++) {
        k_sq<<<sq_blocks, WPB>>>(hop, weight);
        k_agg<<<agg_blocks, WPB>>>(hop, weight, user_emb, entity_emb, out);
    }
}